// round 5
// baseline (speedup 1.0000x reference)
#include <cuda_runtime.h>

#define DK 32
#define ODIM 32
#define MAX_NODES 100002
#define MAX_N 100000
#define NPW 2            // nodes per warp
#define WPB 4            // warps per block (block = 128 threads)

// Scratch (device globals — no allocation in kernel_launch)
__device__ int g_row_ptr[MAX_NODES];
__device__ __align__(16) float g_Agg[MAX_N * DK];

// Kernel 1: build row pointers from sorted dst.
__global__ void build_row_ptr_kernel(const int* __restrict__ dst, int E, int N) {
    int e = blockIdx.x * blockDim.x + threadIdx.x;
    if (e >= E) return;
    int d = dst[e];
    if (e == 0) {
        for (int n = 0; n <= d; ++n) g_row_ptr[n] = 0;
    } else {
        int dp = dst[e - 1];
        for (int n = dp + 1; n <= d; ++n) g_row_ptr[n] = e;
    }
    if (e == E - 1) {
        for (int n = d + 1; n <= N; ++n) g_row_ptr[n] = E;
    }
}

// Kernel 2: edge loop only. Warp handles NPW nodes; 8-lane groups fetch one K
// row + one V row per edge as single LDG.128s. Writes normalized agg rows to
// g_Agg. No smem, no block sync.
__global__ __launch_bounds__(128, 11) void gat_edge_kernel(
    const float* __restrict__ X,
    const float* __restrict__ Kf,
    const float* __restrict__ Vf,
    const int*   __restrict__ src,
    int N)
{
    const unsigned FULL = 0xffffffffu;
    const int lane = threadIdx.x & 31;
    const int warp = (blockIdx.x * blockDim.x + threadIdx.x) >> 5;
    const int node0 = warp * NPW;
    if (node0 >= N) return;

    const int g  = lane >> 3;   // edge slot within a 4-edge sub-batch
    const int qd = lane & 7;    // float4 dim-quad this lane covers

    #pragma unroll
    for (int ni = 0; ni < NPW; ++ni) {
        const int node = node0 + ni;
        if (node >= N) break;
        const int beg = g_row_ptr[node];
        const int end = g_row_ptr[node + 1];

        // Query quad, prescaled by 1/DK (folds the score scaling).
        float4 q4 = *reinterpret_cast<const float4*>(X + (size_t)node * DK + qd * 4);
        q4.x *= (1.f / DK); q4.y *= (1.f / DK); q4.z *= (1.f / DK); q4.w *= (1.f / DK);

        float4 acc = make_float4(0.f, 0.f, 0.f, 0.f);
        float lsum = 0.f;

        // Full (unmasked) iterations: 8 edges = 2 sub-batches of 4.
        int base = beg;
        for (; base + 8 <= end; base += 8) {
            const int sA = __ldg(&src[base + g]);
            const int sB = __ldg(&src[base + 4 + g]);

            const float4 kA = *(reinterpret_cast<const float4*>(Kf + (size_t)sA * DK) + qd);
            const float4 kB = *(reinterpret_cast<const float4*>(Kf + (size_t)sB * DK) + qd);
            const float4 vA = *(reinterpret_cast<const float4*>(Vf + (size_t)sA * DK) + qd);
            const float4 vB = *(reinterpret_cast<const float4*>(Vf + (size_t)sB * DK) + qd);

            float dA = q4.x*kA.x + q4.y*kA.y + q4.z*kA.z + q4.w*kA.w;
            float dB = q4.x*kB.x + q4.y*kB.y + q4.z*kB.z + q4.w*kB.w;
            #pragma unroll
            for (int o = 1; o <= 4; o <<= 1) {
                dA += __shfl_xor_sync(FULL, dA, o);
                dB += __shfl_xor_sync(FULL, dB, o);
            }
            const float pA = __expf(dA);
            const float pB = __expf(dB);
            lsum += pA + pB;
            acc.x += pA * vA.x + pB * vB.x;
            acc.y += pA * vA.y + pB * vB.y;
            acc.z += pA * vA.z + pB * vB.z;
            acc.w += pA * vA.w + pB * vB.w;
        }

        // One masked tail iteration.
        if (base < end) {
            const int eA = base + g;
            const int eB = base + 4 + g;
            const bool vldA = (eA < end);
            const bool vldB = (eB < end);
            const int sA = __ldg(&src[vldA ? eA : beg]);
            const int sB = __ldg(&src[vldB ? eB : beg]);

            const float4 kA = *(reinterpret_cast<const float4*>(Kf + (size_t)sA * DK) + qd);
            const float4 kB = *(reinterpret_cast<const float4*>(Kf + (size_t)sB * DK) + qd);
            const float4 vA = *(reinterpret_cast<const float4*>(Vf + (size_t)sA * DK) + qd);
            const float4 vB = *(reinterpret_cast<const float4*>(Vf + (size_t)sB * DK) + qd);

            float dA = q4.x*kA.x + q4.y*kA.y + q4.z*kA.z + q4.w*kA.w;
            float dB = q4.x*kB.x + q4.y*kB.y + q4.z*kB.z + q4.w*kB.w;
            #pragma unroll
            for (int o = 1; o <= 4; o <<= 1) {
                dA += __shfl_xor_sync(FULL, dA, o);
                dB += __shfl_xor_sync(FULL, dB, o);
            }
            const float pA = vldA ? __expf(dA) : 0.f;
            const float pB = vldB ? __expf(dB) : 0.f;
            lsum += pA + pB;
            acc.x += pA * vA.x + pB * vB.x;
            acc.y += pA * vA.y + pB * vB.y;
            acc.z += pA * vA.z + pB * vB.z;
            acc.w += pA * vA.w + pB * vB.w;
        }

        // Reduce acc + lsum across the 4 edge-groups (bits 3,4 only).
        #pragma unroll
        for (int o = 8; o <= 16; o <<= 1) {
            acc.x += __shfl_xor_sync(FULL, acc.x, o);
            acc.y += __shfl_xor_sync(FULL, acc.y, o);
            acc.z += __shfl_xor_sync(FULL, acc.z, o);
            acc.w += __shfl_xor_sync(FULL, acc.w, o);
            lsum  += __shfl_xor_sync(FULL, lsum,  o);
        }
        const float inv = (lsum > 0.f) ? (1.f / lsum) : 0.f;
        acc.x *= inv; acc.y *= inv; acc.z *= inv; acc.w *= inv;

        // Lanes 0-7 hold quads 0-7: one coalesced 128B row store.
        if (lane < 8)
            *reinterpret_cast<float4*>(&g_Agg[(size_t)node * DK + lane * 4]) = acc;
    }
}

// Kernel 3: dense projection out = Agg @ Wo + b. 64 nodes per block.
__global__ __launch_bounds__(256) void proj_kernel(
    const float* __restrict__ Wo,
    const float* __restrict__ bo,
    float* __restrict__ out,
    int N)
{
    // Transposed Wo with pad: sWoT4[c][dq] = Wo[4dq..4dq+3][c] as float4.
    // Pad to 9 float4s per row -> 16B-aligned rows, conflict-free LDS.128.
    __shared__ float4 sWoT4[ODIM][9];
    __shared__ __align__(16) float sAgg[64][DK];
    __shared__ float sB[ODIM];

    for (int i = threadIdx.x; i < DK * ODIM; i += 256) {
        const int d = i >> 5, c = i & 31;
        reinterpret_cast<float*>(&sWoT4[c][0])[d] = Wo[i];
    }
    if (threadIdx.x < ODIM) sB[threadIdx.x] = bo[threadIdx.x];

    const int tile = blockIdx.x * 64;
    // Load 64 agg rows (512 float4s), guard tail.
    for (int i = threadIdx.x; i < 64 * DK / 4; i += 256) {
        const int gidx = tile * (DK / 4) + i;
        float4 v = make_float4(0.f, 0.f, 0.f, 0.f);
        if (gidx < N * (DK / 4))
            v = *(reinterpret_cast<const float4*>(g_Agg) + gidx);
        *(reinterpret_cast<float4*>(&sAgg[0][0]) + i) = v;
    }
    __syncthreads();

    const int lane = threadIdx.x & 31;
    const int w    = threadIdx.x >> 5;    // warp 0..7 -> local nodes 8w..8w+7

    float o[8];
    #pragma unroll
    for (int n = 0; n < 8; ++n) o[n] = 0.f;

    #pragma unroll
    for (int dq = 0; dq < 8; ++dq) {
        const float4 wt = sWoT4[lane][dq];          // Wo[4dq..][lane]
        #pragma unroll
        for (int n = 0; n < 8; ++n) {
            const float4 a = *reinterpret_cast<const float4*>(&sAgg[w * 8 + n][dq * 4]);
            o[n] += a.x * wt.x + a.y * wt.y + a.z * wt.z + a.w * wt.w;
        }
    }

    const float b = sB[lane];
    #pragma unroll
    for (int n = 0; n < 8; ++n) {
        const int node = tile + w * 8 + n;
        if (node < N)
            out[(size_t)node * ODIM + lane] = o[n] + b;
    }
}

extern "C" void kernel_launch(void* const* d_in, const int* in_sizes, int n_in,
                              void* d_out, int out_size) {
    const float* X   = (const float*)d_in[0];
    const float* K   = (const float*)d_in[1];
    const float* V   = (const float*)d_in[2];
    const float* Wo  = (const float*)d_in[3];
    const float* bo  = (const float*)d_in[4];
    const int*   src = (const int*)d_in[5];
    const int*   dst = (const int*)d_in[6];

    const int N = in_sizes[0] / DK;   // 100000
    const int E = in_sizes[5];        // 1600000

    build_row_ptr_kernel<<<(E + 255) / 256, 256>>>(dst, E, N);

    const int warps   = (N + NPW - 1) / NPW;          // 50000 warps
    const int blocks  = (warps + WPB - 1) / WPB;      // 12500
    gat_edge_kernel<<<blocks, 32 * WPB>>>(X, K, V, src, N);

    const int pblocks = (N + 63) / 64;                // 1563
    proj_kernel<<<pblocks, 256>>>(Wo, bo, (float*)d_out, N);
}